// round 13
// baseline (speedup 1.0000x reference)
#include <cuda_runtime.h>
#include <cuda.h>
#include <cstdint>
#include <cstdio>

// ============================================================================
// Arch-feature dispatch: tcgen05 only exists in compute_103a/sm_103a passes.
// ============================================================================
#if defined(__CUDA_ARCH__) && (defined(__CUDA_ARCH_FEAT_SM103_ALL) || defined(__CUDA_ARCH_FEAT_SM100_ALL))
#define USE_TCGEN05 1
#else
#define USE_TCGEN05 0
#endif

// ============================================================================
// Problem constants
// ============================================================================
#define K_DIM 12288
#define BROWS 8192
#define COUT  1000
#define CPAD  1024

// GEMM tiling
#define M_TILE 128
#define N_TILE 256
#define K_TILE 128
#define STAGES 4
#define K_ITERS (K_DIM / K_TILE)      // 96
#define M_PER_CTA 2
#define A_STAGE_BYTES (M_TILE * K_TILE)               // 16384
#define B_STAGE_BYTES (N_TILE * K_TILE)               // 32768
#define STAGE_BYTES   (A_STAGE_BYTES + B_STAGE_BYTES) // 49152

// Binarize/GEMM handshake: 12 chunks of 8 k-slices (1024 cols) each
#define K_PER_CHUNK 8
#define N_CHUNKS (K_ITERS / K_PER_CHUNK)   // 12
#define CHUNK_COLS (K_PER_CHUNK * K_TILE)  // 1024

// Cluster: 4 CTAs along y share B via TMA multicast slicing
#define CLUSTER_Y 4
#define B_SLICE_ROWS (N_TILE / CLUSTER_Y)             // 64
#define B_SLICE_BYTES (B_SLICE_ROWS * K_TILE)         // 8192
#define MCAST_MASK 0xFu

#define NUM_CTAS 128                  // grid (4, 32)

// SMEM layout
#define SMEM_TMEM_PTR 0
#define SMEM_FULL(s)  (16 + (s) * 8)
#define SMEM_EMPTY(s) (16 + STAGES * 8 + (s) * 8)
#define SMEM_DONE(t)  (16 + 2 * STAGES * 8 + (t) * 8)
#define SMEM_DATA     1024
#define SMEM_BYTES    (SMEM_DATA + STAGES * STAGE_BYTES)   // 197632

// TMEM: two 256-col fp32 accumulators
#define TMEM_D(t) ((t) * 256)
#define TMEM_COLS 512

// idesc for kind::f8f6f4: dtype=F32 (bit4), E4M3 (0), N>>3 @17, M>>4 @24
#define MMA_IDESC ((1u << 4) | ((N_TILE / 8u) << 17) | ((M_TILE / 16u) << 24))

// Fallback tiling constants
#define FB_NIT    (K_DIM / 32)
#define FB_A_ST   (128 * 48)
#define FB_STAGE  (FB_A_ST + 256 * 48)

#define THREADS 512

// ============================================================================
// Scratch (alloc-free rule: __device__ globals)
// ============================================================================
__device__ __align__(1024) unsigned char g_A[(size_t)BROWS * K_DIM];
__device__ __align__(1024) unsigned char g_W[(size_t)CPAD * K_DIM];
__device__ unsigned int g_chunk_cnt[N_CHUNKS];   // zeroed via cudaMemsetAsync per launch

// ============================================================================
// Generic PTX helpers
// ============================================================================
__device__ __forceinline__ uint32_t smem_u32(const void* p) {
    uint32_t a;
    asm("{ .reg .u64 t; cvta.to.shared.u64 t, %1; cvt.u32.u64 %0, t; }" : "=r"(a) : "l"(p));
    return a;
}

#if USE_TCGEN05
__device__ __forceinline__ uint32_t elect_one_pred() {
    uint32_t p;
    asm volatile("{\n\t.reg .pred p;\n\telect.sync _|p, 0xFFFFFFFF;\n\tselp.b32 %0, 1, 0, p;\n\t}" : "=r"(p));
    return p;
}
__device__ __forceinline__ uint32_t cluster_rank() {
    uint32_t r;
    asm("mov.u32 %0, %%cluster_ctarank;" : "=r"(r));
    return r;
}

#define CLUSTER_SYNC() do { \
    asm volatile("barrier.cluster.arrive.aligned;" ::: "memory"); \
    asm volatile("barrier.cluster.wait.aligned;" ::: "memory"); \
} while (0)

#define MBARRIER_INIT(addr, cnt) \
    asm volatile("mbarrier.init.shared.b64 [%0], %1;" :: "r"((uint32_t)(addr)), "r"((uint32_t)(cnt)) : "memory")
#define MBARRIER_EXPECT_TX(addr, bytes) \
    asm volatile("mbarrier.arrive.expect_tx.shared.b64 _, [%0], %1;" :: "r"((uint32_t)(addr)), "r"((uint32_t)(bytes)) : "memory")

#define MBARRIER_WAIT_PARITY(mbar_smem_addr, phase_parity) do { \
    uint32_t _mbar = (uint32_t)(mbar_smem_addr); \
    uint32_t _parity = (uint32_t)(phase_parity); \
    uint32_t _done; \
    asm volatile( \
        "{\n\t.reg .pred p;\n\t" \
        "mbarrier.try_wait.parity.acquire.cta.shared::cta.b64 p, [%1], %2;\n\t" \
        "selp.b32 %0, 1, 0, p;\n\t}" \
        : "=r"(_done) : "r"(_mbar), "r"(_parity) : "memory"); \
    if (!_done) { \
        asm volatile( \
            "{\n\t.reg .pred P1;\n\t" \
            "WAIT_LOOP_%=:\n\t" \
            "mbarrier.try_wait.parity.acquire.cta.shared::cta.b64 P1, [%0], %1, 0x989680;\n\t" \
            "@P1 bra.uni WAIT_DONE_%=;\n\t" \
            "bra.uni WAIT_LOOP_%=;\n\t" \
            "WAIT_DONE_%=:\n\t}" \
            :: "r"(_mbar), "r"(_parity) : "memory"); \
    } \
} while (0)

#define TCGEN05_ALLOC(smem_addr, n) \
    asm volatile("tcgen05.alloc.cta_group::1.sync.aligned.shared::cta.b32 [%0], %1;" \
                 :: "r"((uint32_t)(smem_addr)), "r"((uint32_t)(n)) : "memory")
#define TCGEN05_DEALLOC(tmem, n) \
    asm volatile("tcgen05.dealloc.cta_group::1.sync.aligned.b32 %0, %1;" :: "r"(tmem), "r"((uint32_t)(n)))
#define TCGEN05_RELINQUISH() \
    asm volatile("tcgen05.relinquish_alloc_permit.cta_group::1.sync.aligned;")
#define TCGEN05_COMMIT(mbar) \
    asm volatile("tcgen05.commit.cta_group::1.mbarrier::arrive::one.shared::cluster.b64 [%0];" \
                 :: "r"((uint32_t)(mbar)) : "memory")
#define TCGEN05_COMMIT_MC(mbar, mask) \
    asm volatile("tcgen05.commit.cta_group::1.mbarrier::arrive::one.shared::cluster.multicast::cluster.b64 [%0], %1;" \
                 :: "r"((uint32_t)(mbar)), "h"((uint16_t)(mask)) : "memory")
#define TCGEN05_WAIT_LD() asm volatile("tcgen05.wait::ld.sync.aligned;" ::: "memory")
#define TCGEN05_FENCE_BEFORE() asm volatile("tcgen05.fence::before_thread_sync;" ::: "memory")
#define TCGEN05_FENCE_AFTER()  asm volatile("tcgen05.fence::after_thread_sync;" ::: "memory")

#define TCGEN05_LD_32X32B_X32(r, tmem_addr) \
    asm volatile( \
        "tcgen05.ld.sync.aligned.32x32b.x32.b32 " \
        "{%0, %1, %2, %3, %4, %5, %6, %7, " \
        " %8, %9, %10, %11, %12, %13, %14, %15, " \
        " %16, %17, %18, %19, %20, %21, %22, %23, " \
        " %24, %25, %26, %27, %28, %29, %30, %31}, [%32];" \
        : "=r"((r)[0]),  "=r"((r)[1]),  "=r"((r)[2]),  "=r"((r)[3]), \
          "=r"((r)[4]),  "=r"((r)[5]),  "=r"((r)[6]),  "=r"((r)[7]), \
          "=r"((r)[8]),  "=r"((r)[9]),  "=r"((r)[10]), "=r"((r)[11]), \
          "=r"((r)[12]), "=r"((r)[13]), "=r"((r)[14]), "=r"((r)[15]), \
          "=r"((r)[16]), "=r"((r)[17]), "=r"((r)[18]), "=r"((r)[19]), \
          "=r"((r)[20]), "=r"((r)[21]), "=r"((r)[22]), "=r"((r)[23]), \
          "=r"((r)[24]), "=r"((r)[25]), "=r"((r)[26]), "=r"((r)[27]), \
          "=r"((r)[28]), "=r"((r)[29]), "=r"((r)[30]), "=r"((r)[31]) \
        : "r"(tmem_addr))

static constexpr uint64_t SMEM_DESC_BASE_SW128 =
    (uint64_t(2) << 61) | (uint64_t(1) << 46) | (uint64_t(64) << 32) | (uint64_t(1) << 16);
#define MAKE_SMEM_DESC(base_addr) (SMEM_DESC_BASE_SW128 | ((uint64_t)((base_addr) >> 4) & 0x3FFF))

__device__ __forceinline__ void tma_load_2d(uint32_t smem_addr, const void* map,
                                            int cx, int cy, uint32_t mbar) {
    asm volatile(
        "cp.async.bulk.tensor.2d.shared::cta.global.tile.mbarrier::complete_tx::bytes "
        "[%0], [%1, {%2, %3}], [%4];"
        :: "r"(smem_addr), "l"(map), "r"(cx), "r"(cy), "r"(mbar) : "memory");
}
__device__ __forceinline__ void tma_load_2d_mc(uint32_t smem_addr, const void* map,
                                               int cx, int cy, uint32_t mbar, uint16_t mask) {
    asm volatile(
        "cp.async.bulk.tensor.2d.shared::cluster.global.tile.mbarrier::complete_tx::bytes.multicast::cluster "
        "[%0], [%1, {%2, %3}], [%4], %5;"
        :: "r"(smem_addr), "l"(map), "r"(cx), "r"(cy), "r"(mbar), "h"(mask) : "memory");
}

__device__ __forceinline__ void mma_f8_ss(uint32_t d_tmem, uint64_t a_desc, uint64_t b_desc,
                                          uint32_t idesc, bool acc) {
    uint32_t en = acc ? 1u : 0u;
    asm volatile(
        "{\n\t.reg .pred p;\n\t"
        "setp.ne.u32 p, %4, 0;\n\t"
        "tcgen05.mma.cta_group::1.kind::f8f6f4 [%0], %1, %2, %3, p;\n\t}"
        :: "r"(d_tmem), "l"(a_desc), "l"(b_desc), "r"(idesc), "r"(en) : "memory");
}

// Poll a chunk completion flag (gpu-scope acquire pairs with producer release).
__device__ __forceinline__ void wait_chunk(int c) {
    unsigned int v;
    for (;;) {
        asm volatile("ld.acquire.gpu.global.u32 %0, [%1];"
                     : "=r"(v) : "l"(g_chunk_cnt + c) : "memory");
        if (v >= NUM_CTAS) break;
        __nanosleep(128);
    }
}
#else  // legacy helpers
__device__ __forceinline__ void ldsm_x4(uint32_t* r, uint32_t addr) {
    asm volatile("ldmatrix.sync.aligned.m8n8.x4.shared.b16 {%0,%1,%2,%3}, [%4];"
        : "=r"(r[0]), "=r"(r[1]), "=r"(r[2]), "=r"(r[3]) : "r"(addr));
}
__device__ __forceinline__ void ldsm_x2(uint32_t* r, uint32_t addr) {
    asm volatile("ldmatrix.sync.aligned.m8n8.x2.shared.b16 {%0,%1}, [%2];"
        : "=r"(r[0]), "=r"(r[1]) : "r"(addr));
}
__device__ __forceinline__ void mma_s8(int* c, const uint32_t* a, const uint32_t* b) {
    asm volatile("mma.sync.aligned.m16n8k32.row.col.s32.s8.s8.s32 "
        "{%0,%1,%2,%3}, {%4,%5,%6,%7}, {%8,%9}, {%0,%1,%2,%3};"
        : "+r"(c[0]), "+r"(c[1]), "+r"(c[2]), "+r"(c[3])
        : "r"(a[0]), "r"(a[1]), "r"(a[2]), "r"(a[3]), "r"(b[0]), "r"(b[1]));
}
__device__ __forceinline__ void cp_async16(uint32_t dst, const void* src) {
    asm volatile("cp.async.cg.shared.global [%0], [%1], 16;" :: "r"(dst), "l"(src));
}
#endif

// ============================================================================
// fp32 -> sign byte
// ============================================================================
__device__ __forceinline__ unsigned char sign_byte(float x) {
#if USE_TCGEN05
    return (x == 0.0f) ? 0u : (unsigned char)(0x38u | ((__float_as_uint(x) >> 24) & 0x80u));
#else
    return (x == 0.0f) ? 0u : ((__float_as_uint(x) & 0x80000000u) ? 0xFFu : 0x01u);
#endif
}
__device__ __forceinline__ uint32_t pack4(float4 v) {
    return (uint32_t)sign_byte(v.x) | ((uint32_t)sign_byte(v.y) << 8) |
           ((uint32_t)sign_byte(v.z) << 16) | ((uint32_t)sign_byte(v.w) << 24);
}

// ============================================================================
// FUSED kernel: binarize (warps 8-15) overlapped with tcgen05 GEMM (warps 0-5).
// Grid (4, 32), cluster (1,4,1), 512 threads, one wave.
// Binarize marches chunk-major (12 chunks of 1024 cols), fully coalesced:
// per row, thread t handles the float4 at col 4t -> 4B uchar4 store.
// GEMM producer gates each group of 8 k-iters on the chunk counter.
// ============================================================================
__global__ __launch_bounds__(THREADS, 1) void binary_gemm_kernel(
    float* __restrict__ out,
    const float* __restrict__ finA,
    const float* __restrict__ finW,
    const __grid_constant__ CUtensorMap tma_a,
    const __grid_constant__ CUtensorMap tma_b)
{
#if USE_TCGEN05
    extern __shared__ char smem[];
    uint32_t sb = smem_u32(smem);
    int tid = threadIdx.x;
    int wid = tid >> 5;
    int lane = tid & 31;
    int nblk = blockIdx.x;
    uint32_t rank = cluster_rank();

    if (wid == 5) TCGEN05_ALLOC(sb + SMEM_TMEM_PTR, TMEM_COLS);
    __syncthreads();
    uint32_t tmem;
    asm volatile("ld.shared.b32 %0, [%1];" : "=r"(tmem) : "r"(sb + SMEM_TMEM_PTR));

    if (tid == 0) {
        for (int s = 0; s < STAGES; s++) {
            MBARRIER_INIT(sb + SMEM_FULL(s), 1);
            MBARRIER_INIT(sb + SMEM_EMPTY(s), CLUSTER_Y);
        }
        MBARRIER_INIT(sb + SMEM_DONE(0), 1);
        MBARRIER_INIT(sb + SMEM_DONE(1), 1);
    }
    __syncthreads();
    CLUSTER_SYNC();

    if (wid >= 8) {
        // ---- Binarize producers (coalesced) ----
        int bt = tid - 256;                                // 0..255
        int ctaId = blockIdx.y * gridDim.x + blockIdx.x;   // 0..127
        const int arow0 = ctaId * 64;                      // 64 A-rows per CTA
        const int wrow = ctaId * 8 + (bt >> 5);            // 8 W-rows per CTA
        const int wlane = bt & 31;
        const bool wvalid = (wrow < COUT);

        for (int c = 0; c < N_CHUNKS; ++c) {
            const size_t cb = (size_t)c * CHUNK_COLS;
            // A: 64 rows x 1024 cols. Row r: 256 threads cover cols [0,1024) as
            // lane-contiguous float4 loads (4 lines/instr) + contiguous 4B stores.
            const float* ap = finA + (size_t)arow0 * K_DIM + cb + bt * 4;
            unsigned char* ad = g_A + (size_t)arow0 * K_DIM + cb + bt * 4;
            #pragma unroll 4
            for (int r = 0; r < 64; ++r) {
                float4 v = __ldcs((const float4*)(ap + (size_t)r * K_DIM));
                *(uint32_t*)(ad + (size_t)r * K_DIM) = pack4(v);
            }
            // W: 8 rows x 1024 cols; warp per row, lane-contiguous float4s.
            const float* wp = finW + (size_t)wrow * K_DIM + cb;
            unsigned char* wd = g_W + (size_t)wrow * K_DIM + cb;
            #pragma unroll
            for (int i = 0; i < 8; ++i) {
                int col = (wlane + i * 32) * 4;
                uint32_t o = 0;
                if (wvalid) o = pack4(__ldcs((const float4*)(wp + col)));
                *(uint32_t*)(wd + col) = o;
            }

            asm volatile("bar.sync 9, 256;" ::: "memory");   // 8 binarize warps
            if (bt == 0) {
                asm volatile("membar.gl;" ::: "memory");     // chunk visible gpu-wide
                asm volatile("red.release.gpu.global.add.u32 [%0], 1;"
                             :: "l"(g_chunk_cnt + c) : "memory");
            }
        }
    } else if (wid == 4) {
        // ---- TMA producer: gated per chunk; both tiles interleaved ----
        uint32_t el = elect_one_pred();
        int s = 0, ph = 1;
        for (int it = 0; it < K_ITERS; ++it) {
            if ((it & (K_PER_CHUNK - 1)) == 0) {
                wait_chunk(it / K_PER_CHUNK);
                __syncwarp();
            }
            #pragma unroll
            for (int t = 0; t < M_PER_CTA; ++t) {
                MBARRIER_WAIT_PARITY(sb + SMEM_EMPTY(s), ph);
                if (el) {
                    uint32_t full = sb + SMEM_FULL(s);
                    MBARRIER_EXPECT_TX(full, STAGE_BYTES);
                    uint32_t a_dst = sb + SMEM_DATA + s * STAGE_BYTES;
                    int mrow = (blockIdx.y * M_PER_CTA + t) * M_TILE;
                    tma_load_2d(a_dst, &tma_a, it * K_TILE, mrow, full);
                    uint32_t b_dst = a_dst + A_STAGE_BYTES + rank * B_SLICE_BYTES;
                    tma_load_2d_mc(b_dst, &tma_b, it * K_TILE,
                                   nblk * N_TILE + (int)rank * B_SLICE_ROWS, full,
                                   (uint16_t)MCAST_MASK);
                }
                if (++s == STAGES) { s = 0; ph ^= 1; }
            }
        }
    } else if (wid == 5) {
        // ---- MMA issue: tile t of k-iter it accumulates into TMEM_D(t) ----
        TCGEN05_FENCE_AFTER();
        uint32_t el = elect_one_pred();
        int s = 0, ph = 0;
        for (int it = 0; it < K_ITERS; ++it) {
            #pragma unroll
            for (int t = 0; t < M_PER_CTA; ++t) {
                MBARRIER_WAIT_PARITY(sb + SMEM_FULL(s), ph);
                if (el) {
                    uint32_t a_base = sb + SMEM_DATA + s * STAGE_BYTES;
                    uint64_t ad = MAKE_SMEM_DESC(a_base);
                    uint64_t bd = MAKE_SMEM_DESC(a_base + A_STAGE_BYTES);
                    #pragma unroll
                    for (int k = 0; k < 4; k++) {
                        mma_f8_ss(tmem + TMEM_D(t), ad + k * 2, bd + k * 2, MMA_IDESC,
                                  !(it == 0 && k == 0));
                    }
                    TCGEN05_COMMIT_MC(sb + SMEM_EMPTY(s), MCAST_MASK);
                }
                if (++s == STAGES) { s = 0; ph ^= 1; }
            }
        }
        if (el) {
            TCGEN05_COMMIT(sb + SMEM_DONE(0));
            TCGEN05_COMMIT(sb + SMEM_DONE(1));
        }
    }

    if (wid < 4) {
        // ---- Epilogue ----
        for (int t = 0; t < M_PER_CTA; ++t) {
            MBARRIER_WAIT_PARITY(sb + SMEM_DONE(t), 0);
            TCGEN05_FENCE_AFTER();

            int m = (blockIdx.y * M_PER_CTA + t) * M_TILE + wid * 32 + lane;
            float* orow = out + (size_t)m * COUT;
            int nbase = nblk * N_TILE;
            uint32_t dbase = tmem + TMEM_D(t);

            for (int c0 = 0; c0 < N_TILE; c0 += 32) {
                uint32_t r[32];
                TCGEN05_LD_32X32B_X32(r, dbase + c0);
                TCGEN05_WAIT_LD();
                TCGEN05_FENCE_BEFORE();
                #pragma unroll
                for (int j = 0; j < 32; j += 4) {
                    int n = nbase + c0 + j;
                    if (n < COUT) {
                        float4 v = make_float4(__uint_as_float(r[j]), __uint_as_float(r[j + 1]),
                                               __uint_as_float(r[j + 2]), __uint_as_float(r[j + 3]));
                        *reinterpret_cast<float4*>(orow + n) = v;
                    }
                }
            }
        }
    }

    __syncthreads();
    CLUSTER_SYNC();
    if (wid == 5) {
        TCGEN05_RELINQUISH();
        TCGEN05_DEALLOC(tmem, TMEM_COLS);
    }
#else
    // ------------------------------------------------------------------
    // Fallback: self-binarize then int8 mma.sync (unchanged from R9).
    // ------------------------------------------------------------------
    extern __shared__ char smem[];
    uint32_t sb = smem_u32(smem);
    const int tid = threadIdx.x, lane = tid & 31, wid = tid >> 5;
    const int nblk = blockIdx.x, yb = blockIdx.y;
    const int wm = wid >> 2, wn = wid & 3;

    const int CHUNKS = 256 * (K_DIM / 16);
    for (int i = tid; i < CHUNKS; i += THREADS) {
        int row = yb * 256 + i / (K_DIM / 16);
        int col = (i % (K_DIM / 16)) * 16;
        const float4* p = (const float4*)(finA + (size_t)row * K_DIM + col);
        *(uint4*)(g_A + (size_t)row * K_DIM + col) =
            make_uint4(pack4(__ldcs(p)), pack4(__ldcs(p + 1)),
                       pack4(__ldcs(p + 2)), pack4(__ldcs(p + 3)));
    }
    for (int i = tid; i < CHUNKS; i += THREADS) {
        int row = nblk * 256 + i / (K_DIM / 16);
        int col = (i % (K_DIM / 16)) * 16;
        uint4 o = make_uint4(0, 0, 0, 0);
        if (row < COUT) {
            const float4* p = (const float4*)(finW + (size_t)row * K_DIM + col);
            o = make_uint4(pack4(__ldcs(p)), pack4(__ldcs(p + 1)),
                           pack4(__ldcs(p + 2)), pack4(__ldcs(p + 3)));
        }
        *(uint4*)(g_W + (size_t)row * K_DIM + col) = o;
    }
    __syncthreads();

    for (int t = 0; t < M_PER_CTA; ++t) {
        const int mrow = (yb * M_PER_CTA + t) * 128;

        int c[4][8][4];
        #pragma unroll
        for (int mi = 0; mi < 4; mi++)
            #pragma unroll
            for (int ni = 0; ni < 8; ni++)
                #pragma unroll
                for (int j = 0; j < 4; j++) c[mi][ni][j] = 0;

        auto prefetch = [&](int it, int s) {
            int kb = it * 32;
            #pragma unroll
            for (int tt = 0; tt < 2; tt++) {
                int idx = tid + tt * THREADS;
                if (idx >= 768) break;
                uint32_t dst;
                const unsigned char* src;
                if (idx < 256) {
                    int r = idx >> 1, ch = idx & 1;
                    dst = sb + s * FB_STAGE + (r * 3 + ch) * 16;
                    src = g_A + (size_t)(mrow + r) * K_DIM + kb + ch * 16;
                } else {
                    int j = idx - 256;
                    int r = j >> 1, ch = j & 1;
                    dst = sb + s * FB_STAGE + FB_A_ST + (r * 3 + ch) * 16;
                    src = g_W + (size_t)(nblk * 256 + r) * K_DIM + kb + ch * 16;
                }
                cp_async16(dst, src);
            }
            asm volatile("cp.async.commit_group;" ::: "memory");
        };

        prefetch(0, 0);
        for (int it = 0; it < FB_NIT; ++it) {
            __syncthreads();
            if (it + 1 < FB_NIT) {
                prefetch(it + 1, (it + 1) & 1);
                asm volatile("cp.async.wait_group 1;" ::: "memory");
            } else {
                asm volatile("cp.async.wait_group 0;" ::: "memory");
            }
            __syncthreads();

            if (wid < 8) {
                int s = it & 1;
                uint32_t aB = sb + s * FB_STAGE;
                uint32_t bB = aB + FB_A_ST;

                uint32_t afr[4][4], bfr[8][2];
                #pragma unroll
                for (int mi = 0; mi < 4; mi++) {
                    int row = wm * 64 + mi * 16 + (lane & 15);
                    int ch = lane >> 4;
                    ldsm_x4(afr[mi], aB + (row * 3 + ch) * 16);
                }
                #pragma unroll
                for (int ni = 0; ni < 8; ni++) {
                    int row = wn * 64 + ni * 8 + (lane & 7);
                    int ch = (lane >> 3) & 1;
                    ldsm_x2(bfr[ni], bB + (row * 3 + ch) * 16);
                }
                #pragma unroll
                for (int mi = 0; mi < 4; mi++)
                    #pragma unroll
                    for (int ni = 0; ni < 8; ni++)
                        mma_s8(c[mi][ni], afr[mi], bfr[ni]);
            }
        }
        __syncthreads();

        if (wid < 8) {
            int g = lane >> 2, tig = lane & 3;
            #pragma unroll
            for (int mi = 0; mi < 4; mi++) {
                int m0 = mrow + wm * 64 + mi * 16 + g;
                #pragma unroll
                for (int ni = 0; ni < 8; ni++) {
                    int n0 = nblk * 256 + wn * 64 + ni * 8 + tig * 2;
                    if (n0 < COUT) {
                        out[(size_t)m0 * COUT + n0]       = (float)c[mi][ni][0];
                        out[(size_t)(m0 + 8) * COUT + n0] = (float)c[mi][ni][2];
                    }
                    if (n0 + 1 < COUT) {
                        out[(size_t)m0 * COUT + n0 + 1]       = (float)c[mi][ni][1];
                        out[(size_t)(m0 + 8) * COUT + n0 + 1] = (float)c[mi][ni][3];
                    }
                }
            }
        }
        __syncthreads();
    }
#endif
}

// ============================================================================
// Host launch
// ============================================================================
typedef CUresult (*PFN_TMapEncode)(
    CUtensorMap*, CUtensorMapDataType, cuuint32_t, void*,
    const cuuint64_t*, const cuuint64_t*, const cuuint32_t*, const cuuint32_t*,
    CUtensorMapInterleave, CUtensorMapSwizzle, CUtensorMapL2promotion, CUtensorMapFloatOOBfill);

extern "C" void kernel_launch(void* const* d_in, const int* in_sizes, int n_in,
                              void* d_out, int out_size) {
    const float* inp = (const float*)d_in[0];
    const float* wgt = (const float*)d_in[1];
    if (in_sizes[0] == COUT * K_DIM) { inp = (const float*)d_in[1]; wgt = (const float*)d_in[0]; }
    float* out = (float*)d_out;

    void* pA = nullptr;
    void* pW = nullptr;
    void* pCnt = nullptr;
    cudaGetSymbolAddress(&pA, g_A);
    cudaGetSymbolAddress(&pW, g_W);
    cudaGetSymbolAddress(&pCnt, g_chunk_cnt);

    // Reset chunk flags each launch (graph-replay safe, no alloc)
    cudaMemsetAsync(pCnt, 0, N_CHUNKS * sizeof(unsigned int));

    // TMA descriptors
    PFN_TMapEncode enc = nullptr;
    {
        void* fp = nullptr;
        cudaDriverEntryPointQueryResult st;
        cudaGetDriverEntryPointByVersion("cuTensorMapEncodeTiled", &fp, 12000,
                                         cudaEnableDefault, &st);
        enc = (PFN_TMapEncode)fp;
    }

    CUtensorMap mapA, mapB;
    if (enc) {
        {
            cuuint64_t dims[2] = {K_DIM, BROWS};
            cuuint64_t str[1] = {K_DIM};
            cuuint32_t box[2] = {K_TILE, M_TILE};
            cuuint32_t es[2] = {1, 1};
            enc(&mapA, CU_TENSOR_MAP_DATA_TYPE_UINT8, 2, pA, dims, str, box, es,
                CU_TENSOR_MAP_INTERLEAVE_NONE, CU_TENSOR_MAP_SWIZZLE_128B,
                CU_TENSOR_MAP_L2_PROMOTION_L2_128B, CU_TENSOR_MAP_FLOAT_OOB_FILL_NONE);
        }
        {
            cuuint64_t dims[2] = {K_DIM, CPAD};
            cuuint64_t str[1] = {K_DIM};
            cuuint32_t box[2] = {K_TILE, B_SLICE_ROWS};
            cuuint32_t es[2] = {1, 1};
            enc(&mapB, CU_TENSOR_MAP_DATA_TYPE_UINT8, 2, pW, dims, str, box, es,
                CU_TENSOR_MAP_INTERLEAVE_NONE, CU_TENSOR_MAP_SWIZZLE_128B,
                CU_TENSOR_MAP_L2_PROMOTION_L2_128B, CU_TENSOR_MAP_FLOAT_OOB_FILL_NONE);
        }
    }

    // Fused binarize+GEMM: grid (4, 32) = 128 CTAs, cluster (1,4,1), 512 thr
    cudaFuncSetAttribute(binary_gemm_kernel, cudaFuncAttributeMaxDynamicSharedMemorySize, SMEM_BYTES);

    cudaLaunchConfig_t cfg = {};
    cfg.gridDim = dim3(CPAD / N_TILE, BROWS / (M_TILE * M_PER_CTA), 1);  // (4, 32)
    cfg.blockDim = dim3(THREADS, 1, 1);
    cfg.dynamicSmemBytes = SMEM_BYTES;
    cudaLaunchAttribute attrs[1];
    attrs[0].id = cudaLaunchAttributeClusterDimension;
    attrs[0].val.clusterDim.x = 1;
    attrs[0].val.clusterDim.y = CLUSTER_Y;
    attrs[0].val.clusterDim.z = 1;
    cfg.attrs = attrs;
    cfg.numAttrs = 1;
    cudaLaunchKernelEx(&cfg, binary_gemm_kernel, out, inp, wgt, mapA, mapB);
}

// round 14
// speedup vs baseline: 2.9655x; 2.9655x over previous
#include <cuda_runtime.h>
#include <cuda.h>
#include <cstdint>
#include <cstdio>

// ============================================================================
// Arch-feature dispatch: tcgen05 only exists in compute_103a/sm_103a passes.
// ============================================================================
#if defined(__CUDA_ARCH__) && (defined(__CUDA_ARCH_FEAT_SM103_ALL) || defined(__CUDA_ARCH_FEAT_SM100_ALL))
#define USE_TCGEN05 1
#else
#define USE_TCGEN05 0
#endif

// ============================================================================
// Problem constants
// ============================================================================
#define K_DIM 12288
#define BROWS 8192
#define COUT  1000
#define CPAD  1024

// GEMM tiling
#define M_TILE 128
#define N_TILE 256
#define K_TILE 128
#define STAGES 4
#define K_ITERS (K_DIM / K_TILE)      // 96
#define M_PER_CTA 2
#define A_STAGE_BYTES (M_TILE * K_TILE)               // 16384
#define B_STAGE_BYTES (N_TILE * K_TILE)               // 32768
#define STAGE_BYTES   (A_STAGE_BYTES + B_STAGE_BYTES) // 49152

// Binarize/GEMM handshake: 12 chunks of 8 k-slices (1024 cols) each
#define K_PER_CHUNK 8
#define N_CHUNKS (K_ITERS / K_PER_CHUNK)   // 12
#define CHUNK_COLS (K_PER_CHUNK * K_TILE)  // 1024

// Cluster: 4 CTAs along y share B via TMA multicast slicing
#define CLUSTER_Y 4
#define B_SLICE_ROWS (N_TILE / CLUSTER_Y)             // 64
#define B_SLICE_BYTES (B_SLICE_ROWS * K_TILE)         // 8192
#define MCAST_MASK 0xFu

#define NUM_CTAS 128                  // grid (4, 32)

// SMEM layout
#define SMEM_TMEM_PTR 0
#define SMEM_FULL(s)  (16 + (s) * 8)
#define SMEM_EMPTY(s) (16 + STAGES * 8 + (s) * 8)
#define SMEM_DONE(t)  (16 + 2 * STAGES * 8 + (t) * 8)
#define SMEM_DATA     1024
#define SMEM_BYTES    (SMEM_DATA + STAGES * STAGE_BYTES)   // 197632

// TMEM: two 256-col fp32 accumulators
#define TMEM_D(t) ((t) * 256)
#define TMEM_COLS 512

// idesc for kind::f8f6f4: dtype=F32 (bit4), E4M3 (0), N>>3 @17, M>>4 @24
#define MMA_IDESC ((1u << 4) | ((N_TILE / 8u) << 17) | ((M_TILE / 16u) << 24))

// Fallback tiling constants
#define FB_NIT    (K_DIM / 32)
#define FB_A_ST   (128 * 48)
#define FB_STAGE  (FB_A_ST + 256 * 48)

#define THREADS 512

// ============================================================================
// Scratch (alloc-free rule: __device__ globals)
// ============================================================================
__device__ __align__(1024) unsigned char g_A[(size_t)BROWS * K_DIM];
__device__ __align__(1024) unsigned char g_W[(size_t)CPAD * K_DIM];
__device__ unsigned int g_chunk_cnt[N_CHUNKS];   // zeroed via cudaMemsetAsync per launch

// ============================================================================
// Generic PTX helpers
// ============================================================================
__device__ __forceinline__ uint32_t smem_u32(const void* p) {
    uint32_t a;
    asm("{ .reg .u64 t; cvta.to.shared.u64 t, %1; cvt.u32.u64 %0, t; }" : "=r"(a) : "l"(p));
    return a;
}

#if USE_TCGEN05
__device__ __forceinline__ uint32_t elect_one_pred() {
    uint32_t p;
    asm volatile("{\n\t.reg .pred p;\n\telect.sync _|p, 0xFFFFFFFF;\n\tselp.b32 %0, 1, 0, p;\n\t}" : "=r"(p));
    return p;
}
__device__ __forceinline__ uint32_t cluster_rank() {
    uint32_t r;
    asm("mov.u32 %0, %%cluster_ctarank;" : "=r"(r));
    return r;
}

#define CLUSTER_SYNC() do { \
    asm volatile("barrier.cluster.arrive.aligned;" ::: "memory"); \
    asm volatile("barrier.cluster.wait.aligned;" ::: "memory"); \
} while (0)

#define MBARRIER_INIT(addr, cnt) \
    asm volatile("mbarrier.init.shared.b64 [%0], %1;" :: "r"((uint32_t)(addr)), "r"((uint32_t)(cnt)) : "memory")
#define MBARRIER_EXPECT_TX(addr, bytes) \
    asm volatile("mbarrier.arrive.expect_tx.shared.b64 _, [%0], %1;" :: "r"((uint32_t)(addr)), "r"((uint32_t)(bytes)) : "memory")

#define MBARRIER_WAIT_PARITY(mbar_smem_addr, phase_parity) do { \
    uint32_t _mbar = (uint32_t)(mbar_smem_addr); \
    uint32_t _parity = (uint32_t)(phase_parity); \
    uint32_t _done; \
    asm volatile( \
        "{\n\t.reg .pred p;\n\t" \
        "mbarrier.try_wait.parity.acquire.cta.shared::cta.b64 p, [%1], %2;\n\t" \
        "selp.b32 %0, 1, 0, p;\n\t}" \
        : "=r"(_done) : "r"(_mbar), "r"(_parity) : "memory"); \
    if (!_done) { \
        asm volatile( \
            "{\n\t.reg .pred P1;\n\t" \
            "WAIT_LOOP_%=:\n\t" \
            "mbarrier.try_wait.parity.acquire.cta.shared::cta.b64 P1, [%0], %1, 0x989680;\n\t" \
            "@P1 bra.uni WAIT_DONE_%=;\n\t" \
            "bra.uni WAIT_LOOP_%=;\n\t" \
            "WAIT_DONE_%=:\n\t}" \
            :: "r"(_mbar), "r"(_parity) : "memory"); \
    } \
} while (0)

#define TCGEN05_ALLOC(smem_addr, n) \
    asm volatile("tcgen05.alloc.cta_group::1.sync.aligned.shared::cta.b32 [%0], %1;" \
                 :: "r"((uint32_t)(smem_addr)), "r"((uint32_t)(n)) : "memory")
#define TCGEN05_DEALLOC(tmem, n) \
    asm volatile("tcgen05.dealloc.cta_group::1.sync.aligned.b32 %0, %1;" :: "r"(tmem), "r"((uint32_t)(n)))
#define TCGEN05_RELINQUISH() \
    asm volatile("tcgen05.relinquish_alloc_permit.cta_group::1.sync.aligned;")
#define TCGEN05_COMMIT(mbar) \
    asm volatile("tcgen05.commit.cta_group::1.mbarrier::arrive::one.shared::cluster.b64 [%0];" \
                 :: "r"((uint32_t)(mbar)) : "memory")
#define TCGEN05_COMMIT_MC(mbar, mask) \
    asm volatile("tcgen05.commit.cta_group::1.mbarrier::arrive::one.shared::cluster.multicast::cluster.b64 [%0], %1;" \
                 :: "r"((uint32_t)(mbar)), "h"((uint16_t)(mask)) : "memory")
#define TCGEN05_WAIT_LD() asm volatile("tcgen05.wait::ld.sync.aligned;" ::: "memory")
#define TCGEN05_FENCE_BEFORE() asm volatile("tcgen05.fence::before_thread_sync;" ::: "memory")
#define TCGEN05_FENCE_AFTER()  asm volatile("tcgen05.fence::after_thread_sync;" ::: "memory")

#define TCGEN05_LD_32X32B_X32(r, tmem_addr) \
    asm volatile( \
        "tcgen05.ld.sync.aligned.32x32b.x32.b32 " \
        "{%0, %1, %2, %3, %4, %5, %6, %7, " \
        " %8, %9, %10, %11, %12, %13, %14, %15, " \
        " %16, %17, %18, %19, %20, %21, %22, %23, " \
        " %24, %25, %26, %27, %28, %29, %30, %31}, [%32];" \
        : "=r"((r)[0]),  "=r"((r)[1]),  "=r"((r)[2]),  "=r"((r)[3]), \
          "=r"((r)[4]),  "=r"((r)[5]),  "=r"((r)[6]),  "=r"((r)[7]), \
          "=r"((r)[8]),  "=r"((r)[9]),  "=r"((r)[10]), "=r"((r)[11]), \
          "=r"((r)[12]), "=r"((r)[13]), "=r"((r)[14]), "=r"((r)[15]), \
          "=r"((r)[16]), "=r"((r)[17]), "=r"((r)[18]), "=r"((r)[19]), \
          "=r"((r)[20]), "=r"((r)[21]), "=r"((r)[22]), "=r"((r)[23]), \
          "=r"((r)[24]), "=r"((r)[25]), "=r"((r)[26]), "=r"((r)[27]), \
          "=r"((r)[28]), "=r"((r)[29]), "=r"((r)[30]), "=r"((r)[31]) \
        : "r"(tmem_addr))

static constexpr uint64_t SMEM_DESC_BASE_SW128 =
    (uint64_t(2) << 61) | (uint64_t(1) << 46) | (uint64_t(64) << 32) | (uint64_t(1) << 16);
#define MAKE_SMEM_DESC(base_addr) (SMEM_DESC_BASE_SW128 | ((uint64_t)((base_addr) >> 4) & 0x3FFF))

__device__ __forceinline__ void tma_load_2d(uint32_t smem_addr, const void* map,
                                            int cx, int cy, uint32_t mbar) {
    asm volatile(
        "cp.async.bulk.tensor.2d.shared::cta.global.tile.mbarrier::complete_tx::bytes "
        "[%0], [%1, {%2, %3}], [%4];"
        :: "r"(smem_addr), "l"(map), "r"(cx), "r"(cy), "r"(mbar) : "memory");
}
__device__ __forceinline__ void tma_load_2d_mc(uint32_t smem_addr, const void* map,
                                               int cx, int cy, uint32_t mbar, uint16_t mask) {
    asm volatile(
        "cp.async.bulk.tensor.2d.shared::cluster.global.tile.mbarrier::complete_tx::bytes.multicast::cluster "
        "[%0], [%1, {%2, %3}], [%4], %5;"
        :: "r"(smem_addr), "l"(map), "r"(cx), "r"(cy), "r"(mbar), "h"(mask) : "memory");
}

__device__ __forceinline__ void mma_f8_ss(uint32_t d_tmem, uint64_t a_desc, uint64_t b_desc,
                                          uint32_t idesc, bool acc) {
    uint32_t en = acc ? 1u : 0u;
    asm volatile(
        "{\n\t.reg .pred p;\n\t"
        "setp.ne.u32 p, %4, 0;\n\t"
        "tcgen05.mma.cta_group::1.kind::f8f6f4 [%0], %1, %2, %3, p;\n\t}"
        :: "r"(d_tmem), "l"(a_desc), "l"(b_desc), "r"(idesc), "r"(en) : "memory");
}

// Poll a chunk completion flag (gpu-scope acquire pairs with producer release).
__device__ __forceinline__ void wait_chunk(int c) {
    unsigned int v;
    for (;;) {
        asm volatile("ld.acquire.gpu.global.u32 %0, [%1];"
                     : "=r"(v) : "l"(g_chunk_cnt + c) : "memory");
        if (v >= NUM_CTAS) break;
        __nanosleep(128);
    }
}
#else  // legacy helpers
__device__ __forceinline__ void ldsm_x4(uint32_t* r, uint32_t addr) {
    asm volatile("ldmatrix.sync.aligned.m8n8.x4.shared.b16 {%0,%1,%2,%3}, [%4];"
        : "=r"(r[0]), "=r"(r[1]), "=r"(r[2]), "=r"(r[3]) : "r"(addr));
}
__device__ __forceinline__ void ldsm_x2(uint32_t* r, uint32_t addr) {
    asm volatile("ldmatrix.sync.aligned.m8n8.x2.shared.b16 {%0,%1}, [%2];"
        : "=r"(r[0]), "=r"(r[1]) : "r"(addr));
}
__device__ __forceinline__ void mma_s8(int* c, const uint32_t* a, const uint32_t* b) {
    asm volatile("mma.sync.aligned.m16n8k32.row.col.s32.s8.s8.s32 "
        "{%0,%1,%2,%3}, {%4,%5,%6,%7}, {%8,%9}, {%0,%1,%2,%3};"
        : "+r"(c[0]), "+r"(c[1]), "+r"(c[2]), "+r"(c[3])
        : "r"(a[0]), "r"(a[1]), "r"(a[2]), "r"(a[3]), "r"(b[0]), "r"(b[1]));
}
__device__ __forceinline__ void cp_async16(uint32_t dst, const void* src) {
    asm volatile("cp.async.cg.shared.global [%0], [%1], 16;" :: "r"(dst), "l"(src));
}
#endif

// ============================================================================
// fp32 -> sign byte
// ============================================================================
__device__ __forceinline__ unsigned char sign_byte(float x) {
#if USE_TCGEN05
    return (x == 0.0f) ? 0u : (unsigned char)(0x38u | ((__float_as_uint(x) >> 24) & 0x80u));
#else
    return (x == 0.0f) ? 0u : ((__float_as_uint(x) & 0x80000000u) ? 0xFFu : 0x01u);
#endif
}
__device__ __forceinline__ uint32_t pack4(float4 v) {
    return (uint32_t)sign_byte(v.x) | ((uint32_t)sign_byte(v.y) << 8) |
           ((uint32_t)sign_byte(v.z) << 16) | ((uint32_t)sign_byte(v.w) << 24);
}

// ============================================================================
// FUSED kernel: binarize (warps 8-15) overlapped with tcgen05 GEMM (warps 0-5).
// Grid (4, 32), cluster (1,4,1), 512 threads, one wave.
// Producers are BOTH coalesced (lane-contiguous float4 per row: 4 lines/instr)
// AND deep (8 row-strided loads batched into a register array -> MLP=8, 32KB
// in flight per SM > the ~20KB needed to cover DRAM latency at roofline).
// ============================================================================
__global__ __launch_bounds__(THREADS, 1) void binary_gemm_kernel(
    float* __restrict__ out,
    const float* __restrict__ finA,
    const float* __restrict__ finW,
    const __grid_constant__ CUtensorMap tma_a,
    const __grid_constant__ CUtensorMap tma_b)
{
#if USE_TCGEN05
    extern __shared__ char smem[];
    uint32_t sb = smem_u32(smem);
    int tid = threadIdx.x;
    int wid = tid >> 5;
    int lane = tid & 31;
    int nblk = blockIdx.x;
    uint32_t rank = cluster_rank();

    if (wid == 5) TCGEN05_ALLOC(sb + SMEM_TMEM_PTR, TMEM_COLS);
    __syncthreads();
    uint32_t tmem;
    asm volatile("ld.shared.b32 %0, [%1];" : "=r"(tmem) : "r"(sb + SMEM_TMEM_PTR));

    if (tid == 0) {
        for (int s = 0; s < STAGES; s++) {
            MBARRIER_INIT(sb + SMEM_FULL(s), 1);
            MBARRIER_INIT(sb + SMEM_EMPTY(s), CLUSTER_Y);
        }
        MBARRIER_INIT(sb + SMEM_DONE(0), 1);
        MBARRIER_INIT(sb + SMEM_DONE(1), 1);
    }
    __syncthreads();
    CLUSTER_SYNC();

    if (wid >= 8) {
        // ---- Binarize producers: coalesced + MLP=8 ----
        int bt = tid - 256;                                // 0..255
        int ctaId = blockIdx.y * gridDim.x + blockIdx.x;   // 0..127
        const int arow0 = ctaId * 64;                      // 64 A-rows per CTA
        const int wrow0 = ctaId * 8;                       // 8 W-rows per CTA

        for (int c = 0; c < N_CHUNKS; ++c) {
            const size_t cb = (size_t)c * CHUNK_COLS;
            // A: thread bt owns cols [bt*4, bt*4+4) of every row; rows walked
            // in groups of 8 with all 8 loads issued before any pack/store.
            const float* ap = finA + (size_t)arow0 * K_DIM + cb + bt * 4;
            unsigned char* ad = g_A + (size_t)arow0 * K_DIM + cb + bt * 4;
            for (int r0 = 0; r0 < 64; r0 += 8) {
                float4 v[8];
                #pragma unroll
                for (int k = 0; k < 8; ++k)
                    v[k] = __ldcs((const float4*)(ap + (size_t)(r0 + k) * K_DIM));
                #pragma unroll
                for (int k = 0; k < 8; ++k)
                    *(uint32_t*)(ad + (size_t)(r0 + k) * K_DIM) = pack4(v[k]);
            }
            // W: same pattern over the CTA's 8 weight rows (batched, MLP=8).
            const float* wp = finW + (size_t)wrow0 * K_DIM + cb + bt * 4;
            unsigned char* wd = g_W + (size_t)wrow0 * K_DIM + cb + bt * 4;
            {
                float4 v[8];
                #pragma unroll
                for (int k = 0; k < 8; ++k) {
                    if (wrow0 + k < COUT)
                        v[k] = __ldcs((const float4*)(wp + (size_t)k * K_DIM));
                    else
                        v[k] = make_float4(0.f, 0.f, 0.f, 0.f);   // pad rows -> 0 bytes
                }
                #pragma unroll
                for (int k = 0; k < 8; ++k)
                    *(uint32_t*)(wd + (size_t)k * K_DIM) = pack4(v[k]);
            }

            asm volatile("bar.sync 9, 256;" ::: "memory");   // 8 binarize warps
            if (bt == 0) {
                asm volatile("membar.gl;" ::: "memory");     // chunk visible gpu-wide
                asm volatile("red.release.gpu.global.add.u32 [%0], 1;"
                             :: "l"(g_chunk_cnt + c) : "memory");
            }
        }
    } else if (wid == 4) {
        // ---- TMA producer: gated per chunk; both tiles interleaved ----
        uint32_t el = elect_one_pred();
        int s = 0, ph = 1;
        for (int it = 0; it < K_ITERS; ++it) {
            if ((it & (K_PER_CHUNK - 1)) == 0) {
                wait_chunk(it / K_PER_CHUNK);
                __syncwarp();
            }
            #pragma unroll
            for (int t = 0; t < M_PER_CTA; ++t) {
                MBARRIER_WAIT_PARITY(sb + SMEM_EMPTY(s), ph);
                if (el) {
                    uint32_t full = sb + SMEM_FULL(s);
                    MBARRIER_EXPECT_TX(full, STAGE_BYTES);
                    uint32_t a_dst = sb + SMEM_DATA + s * STAGE_BYTES;
                    int mrow = (blockIdx.y * M_PER_CTA + t) * M_TILE;
                    tma_load_2d(a_dst, &tma_a, it * K_TILE, mrow, full);
                    uint32_t b_dst = a_dst + A_STAGE_BYTES + rank * B_SLICE_BYTES;
                    tma_load_2d_mc(b_dst, &tma_b, it * K_TILE,
                                   nblk * N_TILE + (int)rank * B_SLICE_ROWS, full,
                                   (uint16_t)MCAST_MASK);
                }
                if (++s == STAGES) { s = 0; ph ^= 1; }
            }
        }
    } else if (wid == 5) {
        // ---- MMA issue: tile t of k-iter it accumulates into TMEM_D(t) ----
        TCGEN05_FENCE_AFTER();
        uint32_t el = elect_one_pred();
        int s = 0, ph = 0;
        for (int it = 0; it < K_ITERS; ++it) {
            #pragma unroll
            for (int t = 0; t < M_PER_CTA; ++t) {
                MBARRIER_WAIT_PARITY(sb + SMEM_FULL(s), ph);
                if (el) {
                    uint32_t a_base = sb + SMEM_DATA + s * STAGE_BYTES;
                    uint64_t ad = MAKE_SMEM_DESC(a_base);
                    uint64_t bd = MAKE_SMEM_DESC(a_base + A_STAGE_BYTES);
                    #pragma unroll
                    for (int k = 0; k < 4; k++) {
                        mma_f8_ss(tmem + TMEM_D(t), ad + k * 2, bd + k * 2, MMA_IDESC,
                                  !(it == 0 && k == 0));
                    }
                    TCGEN05_COMMIT_MC(sb + SMEM_EMPTY(s), MCAST_MASK);
                }
                if (++s == STAGES) { s = 0; ph ^= 1; }
            }
        }
        if (el) {
            TCGEN05_COMMIT(sb + SMEM_DONE(0));
            TCGEN05_COMMIT(sb + SMEM_DONE(1));
        }
    }

    if (wid < 4) {
        // ---- Epilogue ----
        for (int t = 0; t < M_PER_CTA; ++t) {
            MBARRIER_WAIT_PARITY(sb + SMEM_DONE(t), 0);
            TCGEN05_FENCE_AFTER();

            int m = (blockIdx.y * M_PER_CTA + t) * M_TILE + wid * 32 + lane;
            float* orow = out + (size_t)m * COUT;
            int nbase = nblk * N_TILE;
            uint32_t dbase = tmem + TMEM_D(t);

            for (int c0 = 0; c0 < N_TILE; c0 += 32) {
                uint32_t r[32];
                TCGEN05_LD_32X32B_X32(r, dbase + c0);
                TCGEN05_WAIT_LD();
                TCGEN05_FENCE_BEFORE();
                #pragma unroll
                for (int j = 0; j < 32; j += 4) {
                    int n = nbase + c0 + j;
                    if (n < COUT) {
                        float4 v = make_float4(__uint_as_float(r[j]), __uint_as_float(r[j + 1]),
                                               __uint_as_float(r[j + 2]), __uint_as_float(r[j + 3]));
                        *reinterpret_cast<float4*>(orow + n) = v;
                    }
                }
            }
        }
    }

    __syncthreads();
    CLUSTER_SYNC();
    if (wid == 5) {
        TCGEN05_RELINQUISH();
        TCGEN05_DEALLOC(tmem, TMEM_COLS);
    }
#else
    // ------------------------------------------------------------------
    // Fallback: self-binarize then int8 mma.sync (unchanged).
    // ------------------------------------------------------------------
    extern __shared__ char smem[];
    uint32_t sb = smem_u32(smem);
    const int tid = threadIdx.x, lane = tid & 31, wid = tid >> 5;
    const int nblk = blockIdx.x, yb = blockIdx.y;
    const int wm = wid >> 2, wn = wid & 3;

    const int CHUNKS = 256 * (K_DIM / 16);
    for (int i = tid; i < CHUNKS; i += THREADS) {
        int row = yb * 256 + i / (K_DIM / 16);
        int col = (i % (K_DIM / 16)) * 16;
        const float4* p = (const float4*)(finA + (size_t)row * K_DIM + col);
        *(uint4*)(g_A + (size_t)row * K_DIM + col) =
            make_uint4(pack4(__ldcs(p)), pack4(__ldcs(p + 1)),
                       pack4(__ldcs(p + 2)), pack4(__ldcs(p + 3)));
    }
    for (int i = tid; i < CHUNKS; i += THREADS) {
        int row = nblk * 256 + i / (K_DIM / 16);
        int col = (i % (K_DIM / 16)) * 16;
        uint4 o = make_uint4(0, 0, 0, 0);
        if (row < COUT) {
            const float4* p = (const float4*)(finW + (size_t)row * K_DIM + col);
            o = make_uint4(pack4(__ldcs(p)), pack4(__ldcs(p + 1)),
                           pack4(__ldcs(p + 2)), pack4(__ldcs(p + 3)));
        }
        *(uint4*)(g_W + (size_t)row * K_DIM + col) = o;
    }
    __syncthreads();

    for (int t = 0; t < M_PER_CTA; ++t) {
        const int mrow = (yb * M_PER_CTA + t) * 128;

        int c[4][8][4];
        #pragma unroll
        for (int mi = 0; mi < 4; mi++)
            #pragma unroll
            for (int ni = 0; ni < 8; ni++)
                #pragma unroll
                for (int j = 0; j < 4; j++) c[mi][ni][j] = 0;

        auto prefetch = [&](int it, int s) {
            int kb = it * 32;
            #pragma unroll
            for (int tt = 0; tt < 2; tt++) {
                int idx = tid + tt * THREADS;
                if (idx >= 768) break;
                uint32_t dst;
                const unsigned char* src;
                if (idx < 256) {
                    int r = idx >> 1, ch = idx & 1;
                    dst = sb + s * FB_STAGE + (r * 3 + ch) * 16;
                    src = g_A + (size_t)(mrow + r) * K_DIM + kb + ch * 16;
                } else {
                    int j = idx - 256;
                    int r = j >> 1, ch = j & 1;
                    dst = sb + s * FB_STAGE + FB_A_ST + (r * 3 + ch) * 16;
                    src = g_W + (size_t)(nblk * 256 + r) * K_DIM + kb + ch * 16;
                }
                cp_async16(dst, src);
            }
            asm volatile("cp.async.commit_group;" ::: "memory");
        };

        prefetch(0, 0);
        for (int it = 0; it < FB_NIT; ++it) {
            __syncthreads();
            if (it + 1 < FB_NIT) {
                prefetch(it + 1, (it + 1) & 1);
                asm volatile("cp.async.wait_group 1;" ::: "memory");
            } else {
                asm volatile("cp.async.wait_group 0;" ::: "memory");
            }
            __syncthreads();

            if (wid < 8) {
                int s = it & 1;
                uint32_t aB = sb + s * FB_STAGE;
                uint32_t bB = aB + FB_A_ST;

                uint32_t afr[4][4], bfr[8][2];
                #pragma unroll
                for (int mi = 0; mi < 4; mi++) {
                    int row = wm * 64 + mi * 16 + (lane & 15);
                    int ch = lane >> 4;
                    ldsm_x4(afr[mi], aB + (row * 3 + ch) * 16);
                }
                #pragma unroll
                for (int ni = 0; ni < 8; ni++) {
                    int row = wn * 64 + ni * 8 + (lane & 7);
                    int ch = (lane >> 3) & 1;
                    ldsm_x2(bfr[ni], bB + (row * 3 + ch) * 16);
                }
                #pragma unroll
                for (int mi = 0; mi < 4; mi++)
                    #pragma unroll
                    for (int ni = 0; ni < 8; ni++)
                        mma_s8(c[mi][ni], afr[mi], bfr[ni]);
            }
        }
        __syncthreads();

        if (wid < 8) {
            int g = lane >> 2, tig = lane & 3;
            #pragma unroll
            for (int mi = 0; mi < 4; mi++) {
                int m0 = mrow + wm * 64 + mi * 16 + g;
                #pragma unroll
                for (int ni = 0; ni < 8; ni++) {
                    int n0 = nblk * 256 + wn * 64 + ni * 8 + tig * 2;
                    if (n0 < COUT) {
                        out[(size_t)m0 * COUT + n0]       = (float)c[mi][ni][0];
                        out[(size_t)(m0 + 8) * COUT + n0] = (float)c[mi][ni][2];
                    }
                    if (n0 + 1 < COUT) {
                        out[(size_t)m0 * COUT + n0 + 1]       = (float)c[mi][ni][1];
                        out[(size_t)(m0 + 8) * COUT + n0 + 1] = (float)c[mi][ni][3];
                    }
                }
            }
        }
        __syncthreads();
    }
#endif
}

// ============================================================================
// Host launch
// ============================================================================
typedef CUresult (*PFN_TMapEncode)(
    CUtensorMap*, CUtensorMapDataType, cuuint32_t, void*,
    const cuuint64_t*, const cuuint64_t*, const cuuint32_t*, const cuuint32_t*,
    CUtensorMapInterleave, CUtensorMapSwizzle, CUtensorMapL2promotion, CUtensorMapFloatOOBfill);

extern "C" void kernel_launch(void* const* d_in, const int* in_sizes, int n_in,
                              void* d_out, int out_size) {
    const float* inp = (const float*)d_in[0];
    const float* wgt = (const float*)d_in[1];
    if (in_sizes[0] == COUT * K_DIM) { inp = (const float*)d_in[1]; wgt = (const float*)d_in[0]; }
    float* out = (float*)d_out;

    void* pA = nullptr;
    void* pW = nullptr;
    void* pCnt = nullptr;
    cudaGetSymbolAddress(&pA, g_A);
    cudaGetSymbolAddress(&pW, g_W);
    cudaGetSymbolAddress(&pCnt, g_chunk_cnt);

    // Reset chunk flags each launch (graph-replay safe, no alloc)
    cudaMemsetAsync(pCnt, 0, N_CHUNKS * sizeof(unsigned int));

    // TMA descriptors
    PFN_TMapEncode enc = nullptr;
    {
        void* fp = nullptr;
        cudaDriverEntryPointQueryResult st;
        cudaGetDriverEntryPointByVersion("cuTensorMapEncodeTiled", &fp, 12000,
                                         cudaEnableDefault, &st);
        enc = (PFN_TMapEncode)fp;
    }

    CUtensorMap mapA, mapB;
    if (enc) {
        {
            cuuint64_t dims[2] = {K_DIM, BROWS};
            cuuint64_t str[1] = {K_DIM};
            cuuint32_t box[2] = {K_TILE, M_TILE};
            cuuint32_t es[2] = {1, 1};
            enc(&mapA, CU_TENSOR_MAP_DATA_TYPE_UINT8, 2, pA, dims, str, box, es,
                CU_TENSOR_MAP_INTERLEAVE_NONE, CU_TENSOR_MAP_SWIZZLE_128B,
                CU_TENSOR_MAP_L2_PROMOTION_L2_128B, CU_TENSOR_MAP_FLOAT_OOB_FILL_NONE);
        }
        {
            cuuint64_t dims[2] = {K_DIM, CPAD};
            cuuint64_t str[1] = {K_DIM};
            cuuint32_t box[2] = {K_TILE, B_SLICE_ROWS};
            cuuint32_t es[2] = {1, 1};
            enc(&mapB, CU_TENSOR_MAP_DATA_TYPE_UINT8, 2, pW, dims, str, box, es,
                CU_TENSOR_MAP_INTERLEAVE_NONE, CU_TENSOR_MAP_SWIZZLE_128B,
                CU_TENSOR_MAP_L2_PROMOTION_L2_128B, CU_TENSOR_MAP_FLOAT_OOB_FILL_NONE);
        }
    }

    // Fused binarize+GEMM: grid (4, 32) = 128 CTAs, cluster (1,4,1), 512 thr
    cudaFuncSetAttribute(binary_gemm_kernel, cudaFuncAttributeMaxDynamicSharedMemorySize, SMEM_BYTES);

    cudaLaunchConfig_t cfg = {};
    cfg.gridDim = dim3(CPAD / N_TILE, BROWS / (M_TILE * M_PER_CTA), 1);  // (4, 32)
    cfg.blockDim = dim3(THREADS, 1, 1);
    cfg.dynamicSmemBytes = SMEM_BYTES;
    cudaLaunchAttribute attrs[1];
    attrs[0].id = cudaLaunchAttributeClusterDimension;
    attrs[0].val.clusterDim.x = 1;
    attrs[0].val.clusterDim.y = CLUSTER_Y;
    attrs[0].val.clusterDim.z = 1;
    cfg.attrs = attrs;
    cfg.numAttrs = 1;
    cudaLaunchKernelEx(&cfg, binary_gemm_kernel, out, inp, wgt, mapA, mapB);
}

// round 15
// speedup vs baseline: 3.1216x; 1.0526x over previous
#include <cuda_runtime.h>
#include <cuda.h>
#include <cstdint>
#include <cstdio>

// ============================================================================
// Arch-feature dispatch: tcgen05 only exists in compute_103a/sm_103a passes.
// ============================================================================
#if defined(__CUDA_ARCH__) && (defined(__CUDA_ARCH_FEAT_SM103_ALL) || defined(__CUDA_ARCH_FEAT_SM100_ALL))
#define USE_TCGEN05 1
#else
#define USE_TCGEN05 0
#endif

// ============================================================================
// Problem constants
// ============================================================================
#define K_DIM 12288
#define BROWS 8192
#define COUT  1000
#define CPAD  1024

// GEMM tiling
#define M_TILE 128
#define N_TILE 256
#define K_TILE 128
#define STAGES 4
#define K_ITERS (K_DIM / K_TILE)      // 96
#define M_PER_CTA 2
#define A_STAGE_BYTES (M_TILE * K_TILE)               // 16384
#define B_STAGE_BYTES (N_TILE * K_TILE)               // 32768
#define STAGE_BYTES   (A_STAGE_BYTES + B_STAGE_BYTES) // 49152

// Binarize/GEMM handshake: 12 chunks of 8 k-slices (1024 cols) each
#define K_PER_CHUNK 8
#define N_CHUNKS (K_ITERS / K_PER_CHUNK)   // 12
#define CHUNK_COLS (K_PER_CHUNK * K_TILE)  // 1024

// Producer geometry: warps 0-3 and 6-15 binarize (448 threads)
#define PROD_THREADS 448
#define CHUNK_ITEMS (72 * 256)             // 64 A-rows + 8 W-rows, 256 float4/row

// Cluster: 4 CTAs along y share B via TMA multicast slicing
#define CLUSTER_Y 4
#define B_SLICE_ROWS (N_TILE / CLUSTER_Y)             // 64
#define B_SLICE_BYTES (B_SLICE_ROWS * K_TILE)         // 8192
#define MCAST_MASK 0xFu

#define NUM_CTAS 128                  // grid (4, 32)

// SMEM layout
#define SMEM_TMEM_PTR 0
#define SMEM_FULL(s)  (16 + (s) * 8)
#define SMEM_EMPTY(s) (16 + STAGES * 8 + (s) * 8)
#define SMEM_DONE(t)  (16 + 2 * STAGES * 8 + (t) * 8)
#define SMEM_DATA     1024
#define SMEM_BYTES    (SMEM_DATA + STAGES * STAGE_BYTES)   // 197632

// TMEM: two 256-col fp32 accumulators
#define TMEM_D(t) ((t) * 256)
#define TMEM_COLS 512

// idesc for kind::f8f6f4: dtype=F32 (bit4), E4M3 (0), N>>3 @17, M>>4 @24
#define MMA_IDESC ((1u << 4) | ((N_TILE / 8u) << 17) | ((M_TILE / 16u) << 24))

// Fallback tiling constants
#define FB_NIT    (K_DIM / 32)
#define FB_A_ST   (128 * 48)
#define FB_STAGE  (FB_A_ST + 256 * 48)

#define THREADS 512

// ============================================================================
// Scratch (alloc-free rule: __device__ globals)
// ============================================================================
__device__ __align__(1024) unsigned char g_A[(size_t)BROWS * K_DIM];
__device__ __align__(1024) unsigned char g_W[(size_t)CPAD * K_DIM];
__device__ unsigned int g_chunk_cnt[N_CHUNKS];   // zeroed via cudaMemsetAsync per launch

// ============================================================================
// Generic PTX helpers
// ============================================================================
__device__ __forceinline__ uint32_t smem_u32(const void* p) {
    uint32_t a;
    asm("{ .reg .u64 t; cvta.to.shared.u64 t, %1; cvt.u32.u64 %0, t; }" : "=r"(a) : "l"(p));
    return a;
}

#if USE_TCGEN05
__device__ __forceinline__ uint32_t elect_one_pred() {
    uint32_t p;
    asm volatile("{\n\t.reg .pred p;\n\telect.sync _|p, 0xFFFFFFFF;\n\tselp.b32 %0, 1, 0, p;\n\t}" : "=r"(p));
    return p;
}
__device__ __forceinline__ uint32_t cluster_rank() {
    uint32_t r;
    asm("mov.u32 %0, %%cluster_ctarank;" : "=r"(r));
    return r;
}

#define CLUSTER_SYNC() do { \
    asm volatile("barrier.cluster.arrive.aligned;" ::: "memory"); \
    asm volatile("barrier.cluster.wait.aligned;" ::: "memory"); \
} while (0)

#define MBARRIER_INIT(addr, cnt) \
    asm volatile("mbarrier.init.shared.b64 [%0], %1;" :: "r"((uint32_t)(addr)), "r"((uint32_t)(cnt)) : "memory")
#define MBARRIER_EXPECT_TX(addr, bytes) \
    asm volatile("mbarrier.arrive.expect_tx.shared.b64 _, [%0], %1;" :: "r"((uint32_t)(addr)), "r"((uint32_t)(bytes)) : "memory")

#define MBARRIER_WAIT_PARITY(mbar_smem_addr, phase_parity) do { \
    uint32_t _mbar = (uint32_t)(mbar_smem_addr); \
    uint32_t _parity = (uint32_t)(phase_parity); \
    uint32_t _done; \
    asm volatile( \
        "{\n\t.reg .pred p;\n\t" \
        "mbarrier.try_wait.parity.acquire.cta.shared::cta.b64 p, [%1], %2;\n\t" \
        "selp.b32 %0, 1, 0, p;\n\t}" \
        : "=r"(_done) : "r"(_mbar), "r"(_parity) : "memory"); \
    if (!_done) { \
        asm volatile( \
            "{\n\t.reg .pred P1;\n\t" \
            "WAIT_LOOP_%=:\n\t" \
            "mbarrier.try_wait.parity.acquire.cta.shared::cta.b64 P1, [%0], %1, 0x989680;\n\t" \
            "@P1 bra.uni WAIT_DONE_%=;\n\t" \
            "bra.uni WAIT_LOOP_%=;\n\t" \
            "WAIT_DONE_%=:\n\t}" \
            :: "r"(_mbar), "r"(_parity) : "memory"); \
    } \
} while (0)

#define TCGEN05_ALLOC(smem_addr, n) \
    asm volatile("tcgen05.alloc.cta_group::1.sync.aligned.shared::cta.b32 [%0], %1;" \
                 :: "r"((uint32_t)(smem_addr)), "r"((uint32_t)(n)) : "memory")
#define TCGEN05_DEALLOC(tmem, n) \
    asm volatile("tcgen05.dealloc.cta_group::1.sync.aligned.b32 %0, %1;" :: "r"(tmem), "r"((uint32_t)(n)))
#define TCGEN05_RELINQUISH() \
    asm volatile("tcgen05.relinquish_alloc_permit.cta_group::1.sync.aligned;")
#define TCGEN05_COMMIT(mbar) \
    asm volatile("tcgen05.commit.cta_group::1.mbarrier::arrive::one.shared::cluster.b64 [%0];" \
                 :: "r"((uint32_t)(mbar)) : "memory")
#define TCGEN05_COMMIT_MC(mbar, mask) \
    asm volatile("tcgen05.commit.cta_group::1.mbarrier::arrive::one.shared::cluster.multicast::cluster.b64 [%0], %1;" \
                 :: "r"((uint32_t)(mbar)), "h"((uint16_t)(mask)) : "memory")
#define TCGEN05_WAIT_LD() asm volatile("tcgen05.wait::ld.sync.aligned;" ::: "memory")
#define TCGEN05_FENCE_BEFORE() asm volatile("tcgen05.fence::before_thread_sync;" ::: "memory")
#define TCGEN05_FENCE_AFTER()  asm volatile("tcgen05.fence::after_thread_sync;" ::: "memory")

#define TCGEN05_LD_32X32B_X32(r, tmem_addr) \
    asm volatile( \
        "tcgen05.ld.sync.aligned.32x32b.x32.b32 " \
        "{%0, %1, %2, %3, %4, %5, %6, %7, " \
        " %8, %9, %10, %11, %12, %13, %14, %15, " \
        " %16, %17, %18, %19, %20, %21, %22, %23, " \
        " %24, %25, %26, %27, %28, %29, %30, %31}, [%32];" \
        : "=r"((r)[0]),  "=r"((r)[1]),  "=r"((r)[2]),  "=r"((r)[3]), \
          "=r"((r)[4]),  "=r"((r)[5]),  "=r"((r)[6]),  "=r"((r)[7]), \
          "=r"((r)[8]),  "=r"((r)[9]),  "=r"((r)[10]), "=r"((r)[11]), \
          "=r"((r)[12]), "=r"((r)[13]), "=r"((r)[14]), "=r"((r)[15]), \
          "=r"((r)[16]), "=r"((r)[17]), "=r"((r)[18]), "=r"((r)[19]), \
          "=r"((r)[20]), "=r"((r)[21]), "=r"((r)[22]), "=r"((r)[23]), \
          "=r"((r)[24]), "=r"((r)[25]), "=r"((r)[26]), "=r"((r)[27]), \
          "=r"((r)[28]), "=r"((r)[29]), "=r"((r)[30]), "=r"((r)[31]) \
        : "r"(tmem_addr))

static constexpr uint64_t SMEM_DESC_BASE_SW128 =
    (uint64_t(2) << 61) | (uint64_t(1) << 46) | (uint64_t(64) << 32) | (uint64_t(1) << 16);
#define MAKE_SMEM_DESC(base_addr) (SMEM_DESC_BASE_SW128 | ((uint64_t)((base_addr) >> 4) & 0x3FFF))

__device__ __forceinline__ void tma_load_2d(uint32_t smem_addr, const void* map,
                                            int cx, int cy, uint32_t mbar) {
    asm volatile(
        "cp.async.bulk.tensor.2d.shared::cta.global.tile.mbarrier::complete_tx::bytes "
        "[%0], [%1, {%2, %3}], [%4];"
        :: "r"(smem_addr), "l"(map), "r"(cx), "r"(cy), "r"(mbar) : "memory");
}
__device__ __forceinline__ void tma_load_2d_mc(uint32_t smem_addr, const void* map,
                                               int cx, int cy, uint32_t mbar, uint16_t mask) {
    asm volatile(
        "cp.async.bulk.tensor.2d.shared::cluster.global.tile.mbarrier::complete_tx::bytes.multicast::cluster "
        "[%0], [%1, {%2, %3}], [%4], %5;"
        :: "r"(smem_addr), "l"(map), "r"(cx), "r"(cy), "r"(mbar), "h"(mask) : "memory");
}

__device__ __forceinline__ void mma_f8_ss(uint32_t d_tmem, uint64_t a_desc, uint64_t b_desc,
                                          uint32_t idesc, bool acc) {
    uint32_t en = acc ? 1u : 0u;
    asm volatile(
        "{\n\t.reg .pred p;\n\t"
        "setp.ne.u32 p, %4, 0;\n\t"
        "tcgen05.mma.cta_group::1.kind::f8f6f4 [%0], %1, %2, %3, p;\n\t}"
        :: "r"(d_tmem), "l"(a_desc), "l"(b_desc), "r"(idesc), "r"(en) : "memory");
}

// Poll a chunk completion flag (gpu-scope acquire pairs with producer release).
__device__ __forceinline__ void wait_chunk(int c) {
    unsigned int v;
    for (;;) {
        asm volatile("ld.acquire.gpu.global.u32 %0, [%1];"
                     : "=r"(v) : "l"(g_chunk_cnt + c) : "memory");
        if (v >= NUM_CTAS) break;
        __nanosleep(128);
    }
}
#else  // legacy helpers
__device__ __forceinline__ void ldsm_x4(uint32_t* r, uint32_t addr) {
    asm volatile("ldmatrix.sync.aligned.m8n8.x4.shared.b16 {%0,%1,%2,%3}, [%4];"
        : "=r"(r[0]), "=r"(r[1]), "=r"(r[2]), "=r"(r[3]) : "r"(addr));
}
__device__ __forceinline__ void ldsm_x2(uint32_t* r, uint32_t addr) {
    asm volatile("ldmatrix.sync.aligned.m8n8.x2.shared.b16 {%0,%1}, [%2];"
        : "=r"(r[0]), "=r"(r[1]) : "r"(addr));
}
__device__ __forceinline__ void mma_s8(int* c, const uint32_t* a, const uint32_t* b) {
    asm volatile("mma.sync.aligned.m16n8k32.row.col.s32.s8.s8.s32 "
        "{%0,%1,%2,%3}, {%4,%5,%6,%7}, {%8,%9}, {%0,%1,%2,%3};"
        : "+r"(c[0]), "+r"(c[1]), "+r"(c[2]), "+r"(c[3])
        : "r"(a[0]), "r"(a[1]), "r"(a[2]), "r"(a[3]), "r"(b[0]), "r"(b[1]));
}
__device__ __forceinline__ void cp_async16(uint32_t dst, const void* src) {
    asm volatile("cp.async.cg.shared.global [%0], [%1], 16;" :: "r"(dst), "l"(src));
}
#endif

// ============================================================================
// fp32 -> sign byte
// ============================================================================
__device__ __forceinline__ unsigned char sign_byte(float x) {
#if USE_TCGEN05
    return (x == 0.0f) ? 0u : (unsigned char)(0x38u | ((__float_as_uint(x) >> 24) & 0x80u));
#else
    return (x == 0.0f) ? 0u : ((__float_as_uint(x) & 0x80000000u) ? 0xFFu : 0x01u);
#endif
}
__device__ __forceinline__ uint32_t pack4(float4 v) {
    return (uint32_t)sign_byte(v.x) | ((uint32_t)sign_byte(v.y) << 8) |
           ((uint32_t)sign_byte(v.z) << 16) | ((uint32_t)sign_byte(v.w) << 24);
}

// ============================================================================
// FUSED kernel: binarize (warps 0-3, 6-15 = 448 threads) overlapped with
// tcgen05 GEMM (warp 4 TMA, warp 5 MMA). Grid (4, 32), cluster (1,4,1),
// 512 threads, one wave. Warps 0-3 binarize through all chunks, then run the
// epilogue (DONE barriers only fire after the last chunk anyway, so no
// overlap is lost). Producers: flat-indexed, lane-coalesced, MLP=8 batches;
// 14 warps x 8 x 512B = 56KB in flight per SM.
// ============================================================================
__global__ __launch_bounds__(THREADS, 1) void binary_gemm_kernel(
    float* __restrict__ out,
    const float* __restrict__ finA,
    const float* __restrict__ finW,
    const __grid_constant__ CUtensorMap tma_a,
    const __grid_constant__ CUtensorMap tma_b)
{
#if USE_TCGEN05
    extern __shared__ char smem[];
    uint32_t sb = smem_u32(smem);
    int tid = threadIdx.x;
    int wid = tid >> 5;
    int lane = tid & 31;
    int nblk = blockIdx.x;
    uint32_t rank = cluster_rank();

    if (wid == 5) TCGEN05_ALLOC(sb + SMEM_TMEM_PTR, TMEM_COLS);
    __syncthreads();
    uint32_t tmem;
    asm volatile("ld.shared.b32 %0, [%1];" : "=r"(tmem) : "r"(sb + SMEM_TMEM_PTR));

    if (tid == 0) {
        for (int s = 0; s < STAGES; s++) {
            MBARRIER_INIT(sb + SMEM_FULL(s), 1);
            MBARRIER_INIT(sb + SMEM_EMPTY(s), CLUSTER_Y);
        }
        MBARRIER_INIT(sb + SMEM_DONE(0), 1);
        MBARRIER_INIT(sb + SMEM_DONE(1), 1);
    }
    __syncthreads();
    CLUSTER_SYNC();

    if (wid == 4) {
        // ---- TMA producer: gated per chunk; both tiles interleaved ----
        uint32_t el = elect_one_pred();
        int s = 0, ph = 1;
        for (int it = 0; it < K_ITERS; ++it) {
            if ((it & (K_PER_CHUNK - 1)) == 0) {
                wait_chunk(it / K_PER_CHUNK);
                __syncwarp();
            }
            #pragma unroll
            for (int t = 0; t < M_PER_CTA; ++t) {
                MBARRIER_WAIT_PARITY(sb + SMEM_EMPTY(s), ph);
                if (el) {
                    uint32_t full = sb + SMEM_FULL(s);
                    MBARRIER_EXPECT_TX(full, STAGE_BYTES);
                    uint32_t a_dst = sb + SMEM_DATA + s * STAGE_BYTES;
                    int mrow = (blockIdx.y * M_PER_CTA + t) * M_TILE;
                    tma_load_2d(a_dst, &tma_a, it * K_TILE, mrow, full);
                    uint32_t b_dst = a_dst + A_STAGE_BYTES + rank * B_SLICE_BYTES;
                    tma_load_2d_mc(b_dst, &tma_b, it * K_TILE,
                                   nblk * N_TILE + (int)rank * B_SLICE_ROWS, full,
                                   (uint16_t)MCAST_MASK);
                }
                if (++s == STAGES) { s = 0; ph ^= 1; }
            }
        }
    } else if (wid == 5) {
        // ---- MMA issue: tile t of k-iter it accumulates into TMEM_D(t) ----
        TCGEN05_FENCE_AFTER();
        uint32_t el = elect_one_pred();
        int s = 0, ph = 0;
        for (int it = 0; it < K_ITERS; ++it) {
            #pragma unroll
            for (int t = 0; t < M_PER_CTA; ++t) {
                MBARRIER_WAIT_PARITY(sb + SMEM_FULL(s), ph);
                if (el) {
                    uint32_t a_base = sb + SMEM_DATA + s * STAGE_BYTES;
                    uint64_t ad = MAKE_SMEM_DESC(a_base);
                    uint64_t bd = MAKE_SMEM_DESC(a_base + A_STAGE_BYTES);
                    #pragma unroll
                    for (int k = 0; k < 4; k++) {
                        mma_f8_ss(tmem + TMEM_D(t), ad + k * 2, bd + k * 2, MMA_IDESC,
                                  !(it == 0 && k == 0));
                    }
                    TCGEN05_COMMIT_MC(sb + SMEM_EMPTY(s), MCAST_MASK);
                }
                if (++s == STAGES) { s = 0; ph ^= 1; }
            }
        }
        if (el) {
            TCGEN05_COMMIT(sb + SMEM_DONE(0));
            TCGEN05_COMMIT(sb + SMEM_DONE(1));
        }
    } else {
        // ---- Binarize producers: warps 0-3 and 6-15 (448 threads) ----
        int pt = (wid < 4) ? tid : (tid - 64);             // 0..447
        int ctaId = blockIdx.y * gridDim.x + blockIdx.x;   // 0..127
        const int arow0 = ctaId * 64;                      // 64 A-rows per CTA
        const int wrow0 = ctaId * 8;                       // 8 W-rows per CTA

        for (int c = 0; c < N_CHUNKS; ++c) {
            const size_t cb = (size_t)c * CHUNK_COLS;

            // Flat item space: 72 virtual rows x 256 float4 = 18432 items.
            // vr < 64 -> A row (arow0+vr); else W row (wrow0+vr-64).
            // Item idx -> thread pt + slot*448. Slots 0..39 are always in
            // range (max idx 447+39*448 = 17919 < 18432): 5 unpredicated
            // batches of 8. Slot 40 always valid (max 18367). Slot 41 valid
            // only for pt < 64.
            #pragma unroll
            for (int b = 0; b < 5; ++b) {
                const float* src[8];
                unsigned char* dst[8];
                bool lv[8];
                float4 v[8];
                #pragma unroll
                for (int j = 0; j < 8; ++j) {
                    int idx = pt + (b * 8 + j) * PROD_THREADS;
                    int vr = idx >> 8;
                    int col = (idx & 255) * 4;
                    if (vr < 64) {
                        size_t off = (size_t)(arow0 + vr) * K_DIM + cb + col;
                        src[j] = finA + off; dst[j] = g_A + off; lv[j] = true;
                    } else {
                        int row = wrow0 + (vr - 64);
                        size_t off = (size_t)row * K_DIM + cb + col;
                        src[j] = finW + off; dst[j] = g_W + off; lv[j] = (row < COUT);
                    }
                }
                #pragma unroll
                for (int j = 0; j < 8; ++j)
                    v[j] = lv[j] ? __ldcs((const float4*)src[j])
                                 : make_float4(0.f, 0.f, 0.f, 0.f);
                #pragma unroll
                for (int j = 0; j < 8; ++j)
                    *(uint32_t*)dst[j] = pack4(v[j]);
            }
            // Tail: slots 40 (all threads) and 41 (pt < 64 only)
            {
                const float* src[2];
                unsigned char* dst[2];
                bool lv[2], ex[2];
                float4 v[2];
                #pragma unroll
                for (int j = 0; j < 2; ++j) {
                    int idx = pt + (40 + j) * PROD_THREADS;
                    ex[j] = (idx < CHUNK_ITEMS);
                    int vr = idx >> 8;
                    int col = (idx & 255) * 4;
                    if (vr < 64) {
                        size_t off = (size_t)(arow0 + vr) * K_DIM + cb + col;
                        src[j] = finA + off; dst[j] = g_A + off; lv[j] = ex[j];
                    } else {
                        int row = wrow0 + (vr - 64);
                        size_t off = (size_t)row * K_DIM + cb + col;
                        src[j] = finW + off; dst[j] = g_W + off;
                        lv[j] = ex[j] && (row < COUT);
                    }
                }
                #pragma unroll
                for (int j = 0; j < 2; ++j)
                    v[j] = lv[j] ? __ldcs((const float4*)src[j])
                                 : make_float4(0.f, 0.f, 0.f, 0.f);
                #pragma unroll
                for (int j = 0; j < 2; ++j)
                    if (ex[j]) *(uint32_t*)dst[j] = pack4(v[j]);
            }

            asm volatile("bar.sync 9, %0;" :: "n"(PROD_THREADS) : "memory");
            if (pt == 0) {
                asm volatile("membar.gl;" ::: "memory");     // chunk visible gpu-wide
                asm volatile("red.release.gpu.global.add.u32 [%0], 1;"
                             :: "l"(g_chunk_cnt + c) : "memory");
            }
        }
    }

    if (wid < 4) {
        // ---- Epilogue (after producer duty) ----
        for (int t = 0; t < M_PER_CTA; ++t) {
            MBARRIER_WAIT_PARITY(sb + SMEM_DONE(t), 0);
            TCGEN05_FENCE_AFTER();

            int m = (blockIdx.y * M_PER_CTA + t) * M_TILE + wid * 32 + lane;
            float* orow = out + (size_t)m * COUT;
            int nbase = nblk * N_TILE;
            uint32_t dbase = tmem + TMEM_D(t);

            for (int c0 = 0; c0 < N_TILE; c0 += 32) {
                uint32_t r[32];
                TCGEN05_LD_32X32B_X32(r, dbase + c0);
                TCGEN05_WAIT_LD();
                TCGEN05_FENCE_BEFORE();
                #pragma unroll
                for (int j = 0; j < 32; j += 4) {
                    int n = nbase + c0 + j;
                    if (n < COUT) {
                        float4 v = make_float4(__uint_as_float(r[j]), __uint_as_float(r[j + 1]),
                                               __uint_as_float(r[j + 2]), __uint_as_float(r[j + 3]));
                        *reinterpret_cast<float4*>(orow + n) = v;
                    }
                }
            }
        }
    }

    __syncthreads();
    CLUSTER_SYNC();
    if (wid == 5) {
        TCGEN05_RELINQUISH();
        TCGEN05_DEALLOC(tmem, TMEM_COLS);
    }
#else
    // ------------------------------------------------------------------
    // Fallback: self-binarize then int8 mma.sync (unchanged).
    // ------------------------------------------------------------------
    extern __shared__ char smem[];
    uint32_t sb = smem_u32(smem);
    const int tid = threadIdx.x, lane = tid & 31, wid = tid >> 5;
    const int nblk = blockIdx.x, yb = blockIdx.y;
    const int wm = wid >> 2, wn = wid & 3;

    const int CHUNKS = 256 * (K_DIM / 16);
    for (int i = tid; i < CHUNKS; i += THREADS) {
        int row = yb * 256 + i / (K_DIM / 16);
        int col = (i % (K_DIM / 16)) * 16;
        const float4* p = (const float4*)(finA + (size_t)row * K_DIM + col);
        *(uint4*)(g_A + (size_t)row * K_DIM + col) =
            make_uint4(pack4(__ldcs(p)), pack4(__ldcs(p + 1)),
                       pack4(__ldcs(p + 2)), pack4(__ldcs(p + 3)));
    }
    for (int i = tid; i < CHUNKS; i += THREADS) {
        int row = nblk * 256 + i / (K_DIM / 16);
        int col = (i % (K_DIM / 16)) * 16;
        uint4 o = make_uint4(0, 0, 0, 0);
        if (row < COUT) {
            const float4* p = (const float4*)(finW + (size_t)row * K_DIM + col);
            o = make_uint4(pack4(__ldcs(p)), pack4(__ldcs(p + 1)),
                           pack4(__ldcs(p + 2)), pack4(__ldcs(p + 3)));
        }
        *(uint4*)(g_W + (size_t)row * K_DIM + col) = o;
    }
    __syncthreads();

    for (int t = 0; t < M_PER_CTA; ++t) {
        const int mrow = (yb * M_PER_CTA + t) * 128;

        int c[4][8][4];
        #pragma unroll
        for (int mi = 0; mi < 4; mi++)
            #pragma unroll
            for (int ni = 0; ni < 8; ni++)
                #pragma unroll
                for (int j = 0; j < 4; j++) c[mi][ni][j] = 0;

        auto prefetch = [&](int it, int s) {
            int kb = it * 32;
            #pragma unroll
            for (int tt = 0; tt < 2; tt++) {
                int idx = tid + tt * THREADS;
                if (idx >= 768) break;
                uint32_t dst;
                const unsigned char* src;
                if (idx < 256) {
                    int r = idx >> 1, ch = idx & 1;
                    dst = sb + s * FB_STAGE + (r * 3 + ch) * 16;
                    src = g_A + (size_t)(mrow + r) * K_DIM + kb + ch * 16;
                } else {
                    int j = idx - 256;
                    int r = j >> 1, ch = j & 1;
                    dst = sb + s * FB_STAGE + FB_A_ST + (r * 3 + ch) * 16;
                    src = g_W + (size_t)(nblk * 256 + r) * K_DIM + kb + ch * 16;
                }
                cp_async16(dst, src);
            }
            asm volatile("cp.async.commit_group;" ::: "memory");
        };

        prefetch(0, 0);
        for (int it = 0; it < FB_NIT; ++it) {
            __syncthreads();
            if (it + 1 < FB_NIT) {
                prefetch(it + 1, (it + 1) & 1);
                asm volatile("cp.async.wait_group 1;" ::: "memory");
            } else {
                asm volatile("cp.async.wait_group 0;" ::: "memory");
            }
            __syncthreads();

            if (wid < 8) {
                int s = it & 1;
                uint32_t aB = sb + s * FB_STAGE;
                uint32_t bB = aB + FB_A_ST;

                uint32_t afr[4][4], bfr[8][2];
                #pragma unroll
                for (int mi = 0; mi < 4; mi++) {
                    int row = wm * 64 + mi * 16 + (lane & 15);
                    int ch = lane >> 4;
                    ldsm_x4(afr[mi], aB + (row * 3 + ch) * 16);
                }
                #pragma unroll
                for (int ni = 0; ni < 8; ni++) {
                    int row = wn * 64 + ni * 8 + (lane & 7);
                    int ch = (lane >> 3) & 1;
                    ldsm_x2(bfr[ni], bB + (row * 3 + ch) * 16);
                }
                #pragma unroll
                for (int mi = 0; mi < 4; mi++)
                    #pragma unroll
                    for (int ni = 0; ni < 8; ni++)
                        mma_s8(c[mi][ni], afr[mi], bfr[ni]);
            }
        }
        __syncthreads();

        if (wid < 8) {
            int g = lane >> 2, tig = lane & 3;
            #pragma unroll
            for (int mi = 0; mi < 4; mi++) {
                int m0 = mrow + wm * 64 + mi * 16 + g;
                #pragma unroll
                for (int ni = 0; ni < 8; ni++) {
                    int n0 = nblk * 256 + wn * 64 + ni * 8 + tig * 2;
                    if (n0 < COUT) {
                        out[(size_t)m0 * COUT + n0]       = (float)c[mi][ni][0];
                        out[(size_t)(m0 + 8) * COUT + n0] = (float)c[mi][ni][2];
                    }
                    if (n0 + 1 < COUT) {
                        out[(size_t)m0 * COUT + n0 + 1]       = (float)c[mi][ni][1];
                        out[(size_t)(m0 + 8) * COUT + n0 + 1] = (float)c[mi][ni][3];
                    }
                }
            }
        }
        __syncthreads();
    }
#endif
}

// ============================================================================
// Host launch
// ============================================================================
typedef CUresult (*PFN_TMapEncode)(
    CUtensorMap*, CUtensorMapDataType, cuuint32_t, void*,
    const cuuint64_t*, const cuuint64_t*, const cuuint32_t*, const cuuint32_t*,
    CUtensorMapInterleave, CUtensorMapSwizzle, CUtensorMapL2promotion, CUtensorMapFloatOOBfill);

extern "C" void kernel_launch(void* const* d_in, const int* in_sizes, int n_in,
                              void* d_out, int out_size) {
    const float* inp = (const float*)d_in[0];
    const float* wgt = (const float*)d_in[1];
    if (in_sizes[0] == COUT * K_DIM) { inp = (const float*)d_in[1]; wgt = (const float*)d_in[0]; }
    float* out = (float*)d_out;

    void* pA = nullptr;
    void* pW = nullptr;
    void* pCnt = nullptr;
    cudaGetSymbolAddress(&pA, g_A);
    cudaGetSymbolAddress(&pW, g_W);
    cudaGetSymbolAddress(&pCnt, g_chunk_cnt);

    // Reset chunk flags each launch (graph-replay safe, no alloc)
    cudaMemsetAsync(pCnt, 0, N_CHUNKS * sizeof(unsigned int));

    // TMA descriptors
    PFN_TMapEncode enc = nullptr;
    {
        void* fp = nullptr;
        cudaDriverEntryPointQueryResult st;
        cudaGetDriverEntryPointByVersion("cuTensorMapEncodeTiled", &fp, 12000,
                                         cudaEnableDefault, &st);
        enc = (PFN_TMapEncode)fp;
    }

    CUtensorMap mapA, mapB;
    if (enc) {
        {
            cuuint64_t dims[2] = {K_DIM, BROWS};
            cuuint64_t str[1] = {K_DIM};
            cuuint32_t box[2] = {K_TILE, M_TILE};
            cuuint32_t es[2] = {1, 1};
            enc(&mapA, CU_TENSOR_MAP_DATA_TYPE_UINT8, 2, pA, dims, str, box, es,
                CU_TENSOR_MAP_INTERLEAVE_NONE, CU_TENSOR_MAP_SWIZZLE_128B,
                CU_TENSOR_MAP_L2_PROMOTION_L2_128B, CU_TENSOR_MAP_FLOAT_OOB_FILL_NONE);
        }
        {
            cuuint64_t dims[2] = {K_DIM, CPAD};
            cuuint64_t str[1] = {K_DIM};
            cuuint32_t box[2] = {K_TILE, B_SLICE_ROWS};
            cuuint32_t es[2] = {1, 1};
            enc(&mapB, CU_TENSOR_MAP_DATA_TYPE_UINT8, 2, pW, dims, str, box, es,
                CU_TENSOR_MAP_INTERLEAVE_NONE, CU_TENSOR_MAP_SWIZZLE_128B,
                CU_TENSOR_MAP_L2_PROMOTION_L2_128B, CU_TENSOR_MAP_FLOAT_OOB_FILL_NONE);
        }
    }

    // Fused binarize+GEMM: grid (4, 32) = 128 CTAs, cluster (1,4,1), 512 thr
    cudaFuncSetAttribute(binary_gemm_kernel, cudaFuncAttributeMaxDynamicSharedMemorySize, SMEM_BYTES);

    cudaLaunchConfig_t cfg = {};
    cfg.gridDim = dim3(CPAD / N_TILE, BROWS / (M_TILE * M_PER_CTA), 1);  // (4, 32)
    cfg.blockDim = dim3(THREADS, 1, 1);
    cfg.dynamicSmemBytes = SMEM_BYTES;
    cudaLaunchAttribute attrs[1];
    attrs[0].id = cudaLaunchAttributeClusterDimension;
    attrs[0].val.clusterDim.x = 1;
    attrs[0].val.clusterDim.y = CLUSTER_Y;
    attrs[0].val.clusterDim.z = 1;
    cfg.attrs = attrs;
    cfg.numAttrs = 1;
    cudaLaunchKernelEx(&cfg, binary_gemm_kernel, out, inp, wgt, mapA, mapB);
}